// round 10
// baseline (speedup 1.0000x reference)
#include <cuda_runtime.h>
#include <cuda_bf16.h>
#include <math.h>
#include <stdint.h>

#define T_STEPS 512
#define BATCH   128
#define IN_DIM  64
#define HID     1024
#define OUT_DIM 64
#define GATES   (3 * HID)
#define MROWS   (T_STEPS * BATCH)   // 65536
#define NBLK    128
#define RTHR    512

typedef unsigned long long u64;

// Persistent scratch (device globals -- no allocation anywhere).
__device__ float g_gi[(size_t)MROWS * GATES];        // input-side gates
__device__ float g_h1[(size_t)MROWS * HID];          // layer outputs (fp32)
__device__ __nv_bfloat16 g_h1hi[(size_t)MROWS * HID];// layer outputs, bf16 hi plane
__device__ __nv_bfloat16 g_h1lo[(size_t)MROWS * HID];// layer outputs, bf16 lo plane
__device__ __nv_bfloat16 g_hzero[BATCH * HID];       // zeros (h_{-1})
__device__ __nv_bfloat16 g_wbhi[(size_t)HID * GATES];// w_ih1 transposed [k][n], hi
__device__ __nv_bfloat16 g_wblo[(size_t)HID * GATES];// lo
__device__ unsigned g_bar_gen;
__device__ unsigned g_bar_cnt;

// ---------- helpers ----------
__device__ __forceinline__ void fma2(u64 &d, u64 a, u64 b) {
    asm("fma.rn.f32x2 %0, %1, %2, %0;" : "+l"(d) : "l"(a), "l"(b));
}
__device__ __forceinline__ u64 dup2(float x) {
    u64 r; asm("mov.b64 %0, {%1, %1};" : "=l"(r) : "f"(x)); return r;
}
__device__ __forceinline__ float2 unpk(u64 v) {
    float2 r; asm("mov.b64 {%0, %1}, %2;" : "=f"(r.x), "=f"(r.y) : "l"(v)); return r;
}
__device__ __forceinline__ float4 ldcg_f32x4(const void* p) {
    float4 v;
    asm volatile("ld.global.cg.v4.f32 {%0, %1, %2, %3}, [%4];"
                 : "=f"(v.x), "=f"(v.y), "=f"(v.z), "=f"(v.w) : "l"(p));
    return v;
}
__device__ __forceinline__ float ldcg_f32(const void* p) {
    float v;
    asm volatile("ld.global.cg.f32 %0, [%1];" : "=f"(v) : "l"(p));
    return v;
}
__device__ __forceinline__ void cp16(unsigned d, const void* s) {
    asm volatile("cp.async.cg.shared.global [%0], [%1], 16;" :: "r"(d), "l"(s));
}
__device__ __forceinline__ void ldsm4(uint32_t* r, uint32_t a) {
    asm volatile("ldmatrix.sync.aligned.m8n8.x4.shared.b16 {%0,%1,%2,%3}, [%4];"
                 : "=r"(r[0]), "=r"(r[1]), "=r"(r[2]), "=r"(r[3]) : "r"(a));
}
__device__ __forceinline__ void ldsm2t(uint32_t* r, uint32_t a) {
    asm volatile("ldmatrix.sync.aligned.m8n8.x2.trans.shared.b16 {%0,%1}, [%2];"
                 : "=r"(r[0]), "=r"(r[1]) : "r"(a));
}
__device__ __forceinline__ void mma16816(float* c, const uint32_t* a, const uint32_t* b) {
    asm volatile("mma.sync.aligned.m16n8k16.row.col.f32.bf16.bf16.f32 "
                 "{%0,%1,%2,%3}, {%4,%5,%6,%7}, {%8,%9}, {%0,%1,%2,%3};"
                 : "+f"(c[0]), "+f"(c[1]), "+f"(c[2]), "+f"(c[3])
                 : "r"(a[0]), "r"(a[1]), "r"(a[2]), "r"(a[3]), "r"(b[0]), "r"(b[1]));
}
// swizzles (byte-offset XOR)
__device__ __forceinline__ uint32_t SWA(uint32_t a) { return a ^ ((a >> 3) & 0x10); }  // 32B rows
// 256B-row B tile (GEMM): XOR 16B-chunk column by (row&7)
__device__ __forceinline__ uint32_t SWR(int row, uint32_t c) { return c ^ (((uint32_t)row & 7u) << 4); }

// ---- grid barrier: release/acquire, nanosleep poll ----
__device__ __forceinline__ void grid_bar() {
    __syncthreads();
    if (threadIdx.x == 0) {
        unsigned gen;
        asm volatile("ld.global.relaxed.gpu.u32 %0, [%1];"
                     : "=r"(gen) : "l"(&g_bar_gen));
        asm volatile("fence.acq_rel.gpu;" ::: "memory");
        unsigned prev = atomicAdd(&g_bar_cnt, 1u);
        if (prev == (unsigned)(NBLK - 1)) {
            asm volatile("st.global.relaxed.gpu.u32 [%0], %1;"
                         :: "l"(&g_bar_cnt), "r"(0u) : "memory");
            asm volatile("fence.acq_rel.gpu;" ::: "memory");
            asm volatile("st.global.relaxed.gpu.u32 [%0], %1;"
                         :: "l"(&g_bar_gen), "r"(gen + 1u) : "memory");
        } else {
            unsigned cur;
            do {
                __nanosleep(64);
                asm volatile("ld.global.relaxed.gpu.u32 %0, [%1];"
                             : "=r"(cur) : "l"(&g_bar_gen));
            } while (cur == gen);
            asm volatile("fence.acq_rel.gpu;" ::: "memory");
        }
    }
    __syncthreads();
}

// rec smem layout (bytes)
#define SMEM_BIAS 0
#define SMEM_W    1024                   // W hi: [1024k][24n] bf16, 48B rows = 48 KB
#define SMEM_WLO  (1024 + 49152)         // 50176
#define SMEM_ACT  (50176 + 49152)        // 99328: 16 warps x 4 bufs x 2 KB rings
#define SMEM_TOT  (99328 + 131072)       // 230,400 B
// red buffer (48 KB) aliases SMEM_ACT after the k-loop.

// ============================================================================
// GRU recurrence on mma.sync; warp-private cp.async rings, depth 4, per-block
// chunk rotation. Warp (p=w&3, q=w>>2): m [32p,32p+32) x n24 x k [256q,256q+256).
// ============================================================================
__global__ void __launch_bounds__(RTHR, 1)
gru_rec_mma(const float* __restrict__ w_hh, const float* __restrict__ b_ih,
            const float* __restrict__ b_hh)
{
    extern __shared__ char smem[];
    const int tid  = threadIdx.x;
    const int wid  = tid >> 5;
    const int lane = tid & 31;
    const int bid  = blockIdx.x;
    const int j0   = bid * 8;
    const int p    = wid & 3;
    const int q    = wid >> 2;
    const int rot  = (bid * 5) & 15;          // per-block chunk rotation
    const uint32_t sb = (uint32_t)__cvta_generic_to_shared(smem);

    // persistent W hi/lo: [k][n=gate*8+u], 48B rows (conflict-free for ldsm2t)
    for (int idx = tid; idx < 24 * HID; idx += RTHR) {
        int n = idx >> 10, k = idx & 1023;
        float w = w_hh[((size_t)(n >> 3) * HID + j0 + (n & 7)) * HID + k];
        __nv_bfloat16 hi = __float2bfloat16(w);
        __nv_bfloat16 lo = __float2bfloat16(w - __bfloat162float(hi));
        uint32_t a = (uint32_t)(k * 48 + n * 2);
        *(__nv_bfloat16*)(smem + SMEM_W   + a) = hi;
        *(__nv_bfloat16*)(smem + SMEM_WLO + a) = lo;
    }
    if (tid < 8) {
        float* sB = (float*)(smem + SMEM_BIAS);
        int j = j0 + tid;
        sB[tid]      = b_ih[j] + b_hh[j];
        sB[8 + tid]  = b_ih[HID + j] + b_hh[HID + j];
        sB[16 + tid] = b_ih[2 * HID + j];
        sB[24 + tid] = b_hh[2 * HID + j];
    }
    for (int idx = bid * RTHR + tid; idx < BATCH * HID; idx += NBLK * RTHR)
        g_hzero[idx] = __float2bfloat16(0.0f);
    __syncthreads();
    grid_bar();

    // lane-constant maps
    const int relrow = ((lane >> 3) & 1) * 8 + (lane & 7);
    const int segA   = lane >> 4;
    const uint32_t offA0 = SWA((uint32_t)(relrow * 32 + segA * 16));
    const uint32_t offA1 = SWA((uint32_t)((16 + relrow) * 32 + segA * 16));
    const int rbB = lane & 15;
    // warp-private staging: lane -> plane spl, rows r0, r0+1
    const int spl = lane >> 4;
    const int r0  = (lane & 15) * 2;
    const uint32_t ring0 = sb + SMEM_ACT + (uint32_t)(wid * 8192);   // 4 x 2 KB
    const uint32_t d00 = (uint32_t)(spl * 1024) + SWA((uint32_t)(r0 * 32));
    const uint32_t d01 = (uint32_t)(spl * 1024) + SWA((uint32_t)(r0 * 32 + 16));
    const uint32_t d10 = (uint32_t)(spl * 1024) + SWA((uint32_t)((r0 + 1) * 32));
    const uint32_t d11 = (uint32_t)(spl * 1024) + SWA((uint32_t)((r0 + 1) * 32 + 16));
    const int eu = tid & 7;
    const int em = tid >> 3;

    for (int t = 0; t < T_STEPS; ++t) {
        const __nv_bfloat16* hi_src = t ? g_h1hi + (size_t)(t - 1) * BATCH * HID : g_hzero;
        const __nv_bfloat16* lo_src = t ? g_h1lo + (size_t)(t - 1) * BATCH * HID : g_hzero;
        const __nv_bfloat16* sp = (spl ? lo_src : hi_src)
                                + (size_t)(32 * p + r0) * HID + q * 256;

        // prologue: stage chunks 0..2 (rotated) into ring bufs 0..2
        #pragma unroll
        for (int pre = 0; pre < 3; ++pre) {
            uint32_t base = ring0 + (uint32_t)(pre * 2048);
            const __nv_bfloat16* s = sp + ((rot + pre) & 15) * 16;
            cp16(base + d00, s);       cp16(base + d01, s + 8);
            cp16(base + d10, s + HID); cp16(base + d11, s + HID + 8);
            asm volatile("cp.async.commit_group;");
        }

        // epilogue operand prefetch
        float gir[2], giz[2], gin[2], hpv[2];
        #pragma unroll
        for (int it = 0; it < 2; ++it) {
            int m = em + it * 64;
            const float* gp = g_gi + ((size_t)t * BATCH + m) * GATES + j0 + eu;
            gir[it] = ldcg_f32(gp);
            giz[it] = ldcg_f32(gp + HID);
            gin[it] = ldcg_f32(gp + 2 * HID);
            hpv[it] = t ? ldcg_f32(g_h1 + ((size_t)(t - 1) * BATCH + m) * HID + j0 + eu)
                        : 0.0f;
        }

        float c[2][3][4];
        #pragma unroll
        for (int mt = 0; mt < 2; ++mt)
            #pragma unroll
            for (int g = 0; g < 3; ++g)
                #pragma unroll
                for (int r = 0; r < 4; ++r) c[mt][g][r] = 0.0f;

        #pragma unroll 1
        for (int i = 0; i < 16; ++i) {
            if (i + 3 < 16) {
                uint32_t base = ring0 + (uint32_t)(((i + 3) & 3) * 2048);
                const __nv_bfloat16* s = sp + ((rot + i + 3) & 15) * 16;
                cp16(base + d00, s);       cp16(base + d01, s + 8);
                cp16(base + d10, s + HID); cp16(base + d11, s + HID + 8);
                asm volatile("cp.async.commit_group;");
                asm volatile("cp.async.wait_group 3;");
            } else if (i == 13) {
                asm volatile("cp.async.wait_group 2;");
            } else if (i == 14) {
                asm volatile("cp.async.wait_group 1;");
            } else {
                asm volatile("cp.async.wait_group 0;");
            }
            __syncwarp();

            const int cc = (rot + i) & 15;
            const int kb = q * 256 + cc * 16;
            uint32_t bh[3][2], bl[3][2];
            #pragma unroll
            for (int g = 0; g < 3; ++g) {
                uint32_t a = (uint32_t)((kb + rbB) * 48 + g * 16);
                ldsm2t(bh[g], sb + SMEM_W + a);
                ldsm2t(bl[g], sb + SMEM_WLO + a);
            }
            const uint32_t abase = ring0 + (uint32_t)((i & 3) * 2048);
            #pragma unroll
            for (int mt = 0; mt < 2; ++mt) {
                uint32_t off = mt ? offA1 : offA0;
                uint32_t ah[4], al[4];
                ldsm4(ah, abase + off);
                ldsm4(al, abase + 1024 + off);
                #pragma unroll
                for (int g = 0; g < 3; ++g) {
                    mma16816(c[mt][g], ah, bh[g]);
                    mma16816(c[mt][g], al, bh[g]);
                    mma16816(c[mt][g], ah, bl[g]);
                }
            }
        }

        __syncthreads();   // rings idle; red aliases them
        float* red = (float*)(smem + SMEM_ACT);   // [128 m][24 n][4 q]
        {
            const int rr0 = p * 32 + (lane >> 2);
            const int c2  = (lane & 3) * 2;
            #pragma unroll
            for (int mt = 0; mt < 2; ++mt) {
                int rr = rr0 + mt * 16;
                #pragma unroll
                for (int g = 0; g < 3; ++g) {
                    int nn = g * 8 + c2;
                    red[(rr * 24 + nn) * 4 + q]           = c[mt][g][0];
                    red[(rr * 24 + nn + 1) * 4 + q]       = c[mt][g][1];
                    red[((rr + 8) * 24 + nn) * 4 + q]     = c[mt][g][2];
                    red[((rr + 8) * 24 + nn + 1) * 4 + q] = c[mt][g][3];
                }
            }
        }
        __syncthreads();

        {
            const float* sB = (const float*)(smem + SMEM_BIAS);
            #pragma unroll
            for (int it = 0; it < 2; ++it) {
                int m = em + it * 64;
                float4 vr = *(const float4*)(red + ((size_t)m * 24 + eu) * 4);
                float4 vz = *(const float4*)(red + ((size_t)m * 24 + 8 + eu) * 4);
                float4 vn = *(const float4*)(red + ((size_t)m * 24 + 16 + eu) * 4);
                float ghr = (vr.x + vr.y) + (vr.z + vr.w);
                float ghz = (vz.x + vz.y) + (vz.z + vz.w);
                float ghn = (vn.x + vn.y) + (vn.z + vn.w);
                float rg = 1.0f / (1.0f + expf(-(gir[it] + ghr + sB[eu])));
                float zg = 1.0f / (1.0f + expf(-(giz[it] + ghz + sB[8 + eu])));
                float ng = tanhf(gin[it] + sB[16 + eu] + rg * (ghn + sB[24 + eu]));
                float h  = (1.0f - zg) * ng + zg * hpv[it];

                __nv_bfloat16 hi = __float2bfloat16(h);
                __nv_bfloat16 lo = __float2bfloat16(h - __bfloat162float(hi));
                size_t o = ((size_t)t * BATCH + m) * HID + j0 + eu;
                g_h1hi[o] = hi;
                g_h1lo[o] = lo;
                g_h1[o]   = h;
            }
        }

        grid_bar();
    }
}

// ============================================================================
// Transpose + bf16-split w_ih1: [3072 n][1024 k] fp32 -> [k][n] hi/lo planes.
// ============================================================================
__global__ void __launch_bounds__(256)
conv_w(const float* __restrict__ w)
{
    __shared__ float tile[32][33];
    const int tx = threadIdx.x & 31;
    const int ty = threadIdx.x >> 5;       // 0..7
    const int k0 = blockIdx.x * 32;
    const int n0 = blockIdx.y * 32;
    #pragma unroll
    for (int r = 0; r < 4; ++r)
        tile[ty + r * 8][tx] = w[(size_t)(n0 + ty + r * 8) * HID + k0 + tx];
    __syncthreads();
    #pragma unroll
    for (int r = 0; r < 4; ++r) {
        float v = tile[tx][ty + r * 8];
        __nv_bfloat16 hi = __float2bfloat16(v);
        __nv_bfloat16 lo = __float2bfloat16(v - __bfloat162float(hi));
        size_t o = (size_t)(k0 + ty + r * 8) * GATES + n0 + tx;
        g_wbhi[o] = hi;
        g_wblo[o] = lo;
    }
}

// ============================================================================
// gi1 = h1 @ w_ih1^T on mma.sync (bf16 3-split). Tile 128m x 128n, K=1024.
// ============================================================================
#define GST 16384
__global__ void __launch_bounds__(512)
gemm_bf16_3s(float* __restrict__ C)
{
    extern __shared__ char gsm[];   // 4 * 16384
    const int tid  = threadIdx.x;
    const int wid  = tid >> 5;
    const int lane = tid & 31;
    const int m0 = blockIdx.y * 128;
    const int n0 = blockIdx.x * 128;
    const int p  = wid & 3;
    const int nq = wid >> 2;
    const uint32_t sb = (uint32_t)__cvta_generic_to_shared(gsm);

    const int relrow = ((lane >> 3) & 1) * 8 + (lane & 7);
    const int segA   = lane >> 4;
    const uint32_t offA0 = SWA((uint32_t)((p * 32 + relrow) * 32 + segA * 16));
    const uint32_t offA1 = SWA((uint32_t)((p * 32 + 16 + relrow) * 32 + segA * 16));
    const int rbB = lane & 15;
    uint32_t offB[4];
    #pragma unroll
    for (int nt = 0; nt < 4; ++nt)
        offB[nt] = (uint32_t)(8192 + rbB * 256) + SWR(rbB, (uint32_t)(nq * 64 + nt * 16));

    // staging maps
    const bool stA = (tid < 256);
    const int  apl = (tid >> 7) & 1;
    const int  am  = tid & 127;
    const int  bix = tid & 255;
    const int  bpl = bix >> 7;
    const int  brw = (bix & 127) >> 3;
    const int  bcs = (bix & 7) * 32;

    const __nv_bfloat16* Asrc = (apl ? g_h1lo : g_h1hi) + (size_t)(m0 + am) * HID;
    const __nv_bfloat16* Bpl  = (bpl ? g_wblo : g_wbhi) + n0 + bcs / 2;
    const uint32_t adst0 = (uint32_t)(apl * 4096) + SWA((uint32_t)(am * 32));
    const uint32_t adst1 = (uint32_t)(apl * 4096) + SWA((uint32_t)(am * 32 + 16));
    const uint32_t bdst0 = (uint32_t)(8192 + bpl * 4096 + brw * 256)
                         + SWR(brw, (uint32_t)bcs);
    const uint32_t bdst1 = (uint32_t)(8192 + bpl * 4096 + brw * 256)
                         + SWR(brw, (uint32_t)(bcs + 16));

    float c[2][4][4];
    #pragma unroll
    for (int mt = 0; mt < 2; ++mt)
        #pragma unroll
        for (int nt = 0; nt < 4; ++nt)
            #pragma unroll
            for (int r = 0; r < 4; ++r) c[mt][nt][r] = 0.0f;

    #pragma unroll
    for (int pre = 0; pre < 3; ++pre) {
        uint32_t base = sb + (uint32_t)(pre * GST);
        if (stA) {
            cp16(base + adst0, Asrc + pre * 16);
            cp16(base + adst1, Asrc + pre * 16 + 8);
        } else {
            const __nv_bfloat16* s = Bpl + (size_t)(pre * 16 + brw) * GATES;
            cp16(base + bdst0, s);
            cp16(base + bdst1, s + 8);
        }
        asm volatile("cp.async.commit_group;");
    }

    #pragma unroll 1
    for (int i = 0; i < 64; ++i) {
        __syncthreads();
        if (i + 3 < 64) {
            uint32_t base = sb + (uint32_t)(((i + 3) & 3) * GST);
            if (stA) {
                cp16(base + adst0, Asrc + (i + 3) * 16);
                cp16(base + adst1, Asrc + (i + 3) * 16 + 8);
            } else {
                const __nv_bfloat16* s = Bpl + (size_t)((i + 3) * 16 + brw) * GATES;
                cp16(base + bdst0, s);
                cp16(base + bdst1, s + 8);
            }
            asm volatile("cp.async.commit_group;");
            asm volatile("cp.async.wait_group 3;");
        } else {
            asm volatile("cp.async.wait_group 0;");
        }
        __syncthreads();

        const uint32_t base = sb + (uint32_t)((i & 3) * GST);
        uint32_t bh[4][2], bl[4][2];
        #pragma unroll
        for (int nt = 0; nt < 4; ++nt) {
            ldsm2t(bh[nt], base + offB[nt]);
            ldsm2t(bl[nt], base + offB[nt] + 4096);
        }
        #pragma unroll
        for (int mt = 0; mt < 2; ++mt) {
            uint32_t off = mt ? offA1 : offA0;
            uint32_t ah[4], al[4];
            ldsm4(ah, base + off);
            ldsm4(al, base + 4096 + off);
            #pragma unroll
            for (int nt = 0; nt < 4; ++nt) {
                mma16816(c[mt][nt], ah, bh[nt]);
                mma16816(c[mt][nt], al, bh[nt]);
                mma16816(c[mt][nt], ah, bl[nt]);
            }
        }
    }

    #pragma unroll
    for (int mt = 0; mt < 2; ++mt) {
        int row = m0 + p * 32 + mt * 16 + (lane >> 2);
        #pragma unroll
        for (int nt = 0; nt < 4; ++nt) {
            int col = n0 + nq * 32 + nt * 8 + (lane & 3) * 2;
            *(float2*)(C + (size_t)row * GATES + col) =
                make_float2(c[mt][nt][0], c[mt][nt][1]);
            *(float2*)(C + (size_t)(row + 8) * GATES + col) =
                make_float2(c[mt][nt][2], c[mt][nt][3]);
        }
    }
}

// ============================================================================
// gi0 = x @ w_ih0^T  (K=64, fp32 f32x2)
// ============================================================================
#define GKC 16
__global__ void __launch_bounds__(256)
gemm_tn_f32x2(const float* __restrict__ A, const float* __restrict__ B,
              float* __restrict__ C, int M, int N, int K)
{
    __shared__ float sA[GKC][132];
    __shared__ float sB[GKC][132];
    const int tid = threadIdx.x;
    const int m0  = blockIdx.y * 128;
    const int n0  = blockIdx.x * 128;
    const int ty  = tid >> 4, tx = tid & 15;
    const int sr = tid >> 1;
    const int sk = (tid & 1) * 8;

    u64 acc[4][8];
    #pragma unroll
    for (int p = 0; p < 4; ++p)
        #pragma unroll
        for (int c = 0; c < 8; ++c) acc[p][c] = 0ull;

    const float* Ag = A + (size_t)(m0 + sr) * K + sk;
    const float* Bg = B + (size_t)(n0 + sr) * K + sk;
    float4 a0 = ldcg_f32x4(Ag);
    float4 a1 = ldcg_f32x4(Ag + 4);
    float4 b0 = ldcg_f32x4(Bg);
    float4 b1 = ldcg_f32x4(Bg + 4);

    for (int kc = 0; kc < K; kc += GKC) {
        sA[sk + 0][sr] = a0.x; sA[sk + 1][sr] = a0.y;
        sA[sk + 2][sr] = a0.z; sA[sk + 3][sr] = a0.w;
        sA[sk + 4][sr] = a1.x; sA[sk + 5][sr] = a1.y;
        sA[sk + 6][sr] = a1.z; sA[sk + 7][sr] = a1.w;
        sB[sk + 0][sr] = b0.x; sB[sk + 1][sr] = b0.y;
        sB[sk + 2][sr] = b0.z; sB[sk + 3][sr] = b0.w;
        sB[sk + 4][sr] = b1.x; sB[sk + 5][sr] = b1.y;
        sB[sk + 6][sr] = b1.z; sB[sk + 7][sr] = b1.w;
        if (kc + GKC < K) {
            Ag += GKC; Bg += GKC;
            a0 = ldcg_f32x4(Ag);
            a1 = ldcg_f32x4(Ag + 4);
            b0 = ldcg_f32x4(Bg);
            b1 = ldcg_f32x4(Bg + 4);
        }
        __syncthreads();
        #pragma unroll
        for (int kk = 0; kk < GKC; ++kk) {
            ulonglong2 aa = *(const ulonglong2*)(&sA[kk][ty * 8]);
            ulonglong2 ab = *(const ulonglong2*)(&sA[kk][ty * 8 + 4]);
            float4 bv0 = *(const float4*)(&sB[kk][tx * 8]);
            float4 bv1 = *(const float4*)(&sB[kk][tx * 8 + 4]);
            float bs[8] = {bv0.x, bv0.y, bv0.z, bv0.w, bv1.x, bv1.y, bv1.z, bv1.w};
            #pragma unroll
            for (int c = 0; c < 8; ++c) {
                u64 bd = dup2(bs[c]);
                fma2(acc[0][c], aa.x, bd);
                fma2(acc[1][c], aa.y, bd);
                fma2(acc[2][c], ab.x, bd);
                fma2(acc[3][c], ab.y, bd);
            }
        }
        __syncthreads();
    }

    #pragma unroll
    for (int p = 0; p < 4; ++p) {
        float2 v[8];
        #pragma unroll
        for (int c = 0; c < 8; ++c) v[c] = unpk(acc[p][c]);
        int row0 = m0 + ty * 8 + p * 2;
        float* c0 = C + (size_t)row0 * N + n0 + tx * 8;
        float* c1 = c0 + N;
        *(float4*)(c0)     = make_float4(v[0].x, v[1].x, v[2].x, v[3].x);
        *(float4*)(c0 + 4) = make_float4(v[4].x, v[5].x, v[6].x, v[7].x);
        *(float4*)(c1)     = make_float4(v[0].y, v[1].y, v[2].y, v[3].y);
        *(float4*)(c1 + 4) = make_float4(v[4].y, v[5].y, v[6].y, v[7].y);
    }
}

// ============================================================================
// out[t,b,o] = h2[t,b,:] . w_lin[o,:] + b_lin[o]  (h2 in g_h1)
// ============================================================================
__global__ void __launch_bounds__(256)
out_linear(const float* __restrict__ w_lin, const float* __restrict__ b_lin,
           float* __restrict__ out)
{
    __shared__ float sA[16][68];
    __shared__ float sB[16][68];
    const int tid = threadIdx.x;
    const size_t rb = (size_t)blockIdx.x * 64;
    const int ty = tid >> 4;
    const int tx = tid & 15;
    const int li   = tid * 4;
    const int srow = li >> 4;
    const int skk  = li & 15;

    float acc[4][4] = {};

    for (int kc = 0; kc < HID; kc += 16) {
        __syncthreads();
        float4 va = ldcg_f32x4(g_h1 + (rb + srow) * HID + kc + skk);
        sA[skk + 0][srow] = va.x; sA[skk + 1][srow] = va.y;
        sA[skk + 2][srow] = va.z; sA[skk + 3][srow] = va.w;
        float4 vb = *(const float4*)(w_lin + (size_t)srow * HID + kc + skk);
        sB[skk + 0][srow] = vb.x; sB[skk + 1][srow] = vb.y;
        sB[skk + 2][srow] = vb.z; sB[skk + 3][srow] = vb.w;
        __syncthreads();
        #pragma unroll
        for (int kk = 0; kk < 16; ++kk) {
            float4 a = *(const float4*)&sA[kk][ty * 4];
            float4 b = *(const float4*)&sB[kk][tx * 4];
            acc[0][0] = fmaf(a.x, b.x, acc[0][0]); acc[0][1] = fmaf(a.x, b.y, acc[0][1]);
            acc[0][2] = fmaf(a.x, b.z, acc[0][2]); acc[0][3] = fmaf(a.x, b.w, acc[0][3]);
            acc[1][0] = fmaf(a.y, b.x, acc[1][0]); acc[1][1] = fmaf(a.y, b.y, acc[1][1]);
            acc[1][2] = fmaf(a.y, b.z, acc[1][2]); acc[1][3] = fmaf(a.y, b.w, acc[1][3]);
            acc[2][0] = fmaf(a.z, b.x, acc[2][0]); acc[2][1] = fmaf(a.z, b.y, acc[2][1]);
            acc[2][2] = fmaf(a.z, b.z, acc[2][2]); acc[2][3] = fmaf(a.z, b.w, acc[2][3]);
            acc[3][0] = fmaf(a.w, b.x, acc[3][0]); acc[3][1] = fmaf(a.w, b.y, acc[3][1]);
            acc[3][2] = fmaf(a.w, b.z, acc[3][2]); acc[3][3] = fmaf(a.w, b.w, acc[3][3]);
        }
    }

    #pragma unroll
    for (int i = 0; i < 4; ++i) {
        float4 o4;
        o4.x = acc[i][0] + b_lin[tx * 4 + 0];
        o4.y = acc[i][1] + b_lin[tx * 4 + 1];
        o4.z = acc[i][2] + b_lin[tx * 4 + 2];
        o4.w = acc[i][3] + b_lin[tx * 4 + 3];
        *(float4*)(out + (rb + ty * 4 + i) * OUT_DIM + tx * 4) = o4;
    }
}

extern "C" void kernel_launch(void* const* d_in, const int* in_sizes, int n_in,
                              void* d_out, int out_size)
{
    const float* x     = (const float*)d_in[0];
    const float* w_ih0 = (const float*)d_in[1];
    const float* w_hh0 = (const float*)d_in[2];
    const float* b_ih0 = (const float*)d_in[3];
    const float* b_hh0 = (const float*)d_in[4];
    const float* w_ih1 = (const float*)d_in[5];
    const float* w_hh1 = (const float*)d_in[6];
    const float* b_ih1 = (const float*)d_in[7];
    const float* b_hh1 = (const float*)d_in[8];
    const float* w_lin = (const float*)d_in[9];
    const float* b_lin = (const float*)d_in[10];
    float* out = (float*)d_out;
    (void)in_sizes; (void)n_in; (void)out_size;

    float *gi_ptr;
    cudaGetSymbolAddress((void**)&gi_ptr, g_gi);

    cudaFuncSetAttribute(gru_rec_mma, cudaFuncAttributeMaxDynamicSharedMemorySize, SMEM_TOT);
    cudaFuncSetAttribute(gemm_bf16_3s, cudaFuncAttributeMaxDynamicSharedMemorySize, 4 * GST);

    // w_ih1 transpose + split (independent of layer 0)
    conv_w<<<dim3(HID / 32, GATES / 32), 256>>>(w_ih1);

    // layer 0
    gemm_tn_f32x2<<<dim3(GATES / 128, MROWS / 128), 256>>>(x, w_ih0, gi_ptr,
                                                           MROWS, GATES, IN_DIM);
    gru_rec_mma<<<NBLK, RTHR, SMEM_TOT>>>(w_hh0, b_ih0, b_hh0);

    // layer 1
    gemm_bf16_3s<<<dim3(GATES / 128, MROWS / 128), 512, 4 * GST>>>(gi_ptr);
    gru_rec_mma<<<NBLK, RTHR, SMEM_TOT>>>(w_hh1, b_ih1, b_hh1);

    // time-distributed linear
    out_linear<<<MROWS / 64, 256>>>(w_lin, b_lin, out);
}

// round 11
// speedup vs baseline: 1.4515x; 1.4515x over previous
#include <cuda_runtime.h>
#include <cuda_bf16.h>
#include <math.h>
#include <stdint.h>

#define T_STEPS 512
#define BATCH   128
#define IN_DIM  64
#define HID     1024
#define OUT_DIM 64
#define GATES   (3 * HID)
#define MROWS   (T_STEPS * BATCH)   // 65536
#define NBLK    128
#define RTHR    512

typedef unsigned long long u64;

// Persistent scratch (device globals -- no allocation anywhere).
__device__ float g_gi[(size_t)MROWS * GATES];        // input-side gates
__device__ float g_h1[(size_t)MROWS * HID];          // layer outputs (fp32)
__device__ __nv_bfloat16 g_h1hi[(size_t)MROWS * HID];// layer outputs, bf16 hi plane
__device__ __nv_bfloat16 g_h1lo[(size_t)MROWS * HID];// layer outputs, bf16 lo plane
__device__ __nv_bfloat16 g_hzero[BATCH * HID];       // zeros (h_{-1})
__device__ __nv_bfloat16 g_wbhi[(size_t)HID * GATES];// w_ih1 transposed [k][n], hi
__device__ __nv_bfloat16 g_wblo[(size_t)HID * GATES];// lo
__device__ unsigned g_bar_gen;
__device__ unsigned g_bar_cnt;

// ---------- helpers ----------
__device__ __forceinline__ void fma2(u64 &d, u64 a, u64 b) {
    asm("fma.rn.f32x2 %0, %1, %2, %0;" : "+l"(d) : "l"(a), "l"(b));
}
__device__ __forceinline__ u64 dup2(float x) {
    u64 r; asm("mov.b64 %0, {%1, %1};" : "=l"(r) : "f"(x)); return r;
}
__device__ __forceinline__ float2 unpk(u64 v) {
    float2 r; asm("mov.b64 {%0, %1}, %2;" : "=f"(r.x), "=f"(r.y) : "l"(v)); return r;
}
__device__ __forceinline__ float4 ldcg_f32x4(const void* p) {
    float4 v;
    asm volatile("ld.global.cg.v4.f32 {%0, %1, %2, %3}, [%4];"
                 : "=f"(v.x), "=f"(v.y), "=f"(v.z), "=f"(v.w) : "l"(p));
    return v;
}
__device__ __forceinline__ float ldcg_f32(const void* p) {
    float v;
    asm volatile("ld.global.cg.f32 %0, [%1];" : "=f"(v) : "l"(p));
    return v;
}
__device__ __forceinline__ void cp16(unsigned d, const void* s) {
    asm volatile("cp.async.cg.shared.global [%0], [%1], 16;" :: "r"(d), "l"(s));
}
__device__ __forceinline__ void ldsm4(uint32_t* r, uint32_t a) {
    asm volatile("ldmatrix.sync.aligned.m8n8.x4.shared.b16 {%0,%1,%2,%3}, [%4];"
                 : "=r"(r[0]), "=r"(r[1]), "=r"(r[2]), "=r"(r[3]) : "r"(a));
}
__device__ __forceinline__ void ldsm2t(uint32_t* r, uint32_t a) {
    asm volatile("ldmatrix.sync.aligned.m8n8.x2.trans.shared.b16 {%0,%1}, [%2];"
                 : "=r"(r[0]), "=r"(r[1]) : "r"(a));
}
__device__ __forceinline__ void mma16816(float* c, const uint32_t* a, const uint32_t* b) {
    asm volatile("mma.sync.aligned.m16n8k16.row.col.f32.bf16.bf16.f32 "
                 "{%0,%1,%2,%3}, {%4,%5,%6,%7}, {%8,%9}, {%0,%1,%2,%3};"
                 : "+f"(c[0]), "+f"(c[1]), "+f"(c[2]), "+f"(c[3])
                 : "r"(a[0]), "r"(a[1]), "r"(a[2]), "r"(a[3]), "r"(b[0]), "r"(b[1]));
}
// swizzles (byte-offset XOR)
__device__ __forceinline__ uint32_t SWA(uint32_t a) { return a ^ ((a >> 3) & 0x10); }   // 32B rows
__device__ __forceinline__ uint32_t SW128(uint32_t a){ return a ^ ((a >> 3) & 0x70); }  // 128B rows
// 256B-row B tile (GEMM): XOR 16B-chunk column by (row&7)
__device__ __forceinline__ uint32_t SWR(int row, uint32_t c) { return c ^ (((uint32_t)row & 7u) << 4); }

// ---- grid barrier: release/acquire, nanosleep poll ----
__device__ __forceinline__ void grid_bar() {
    __syncthreads();
    if (threadIdx.x == 0) {
        unsigned gen;
        asm volatile("ld.global.relaxed.gpu.u32 %0, [%1];"
                     : "=r"(gen) : "l"(&g_bar_gen));
        asm volatile("fence.acq_rel.gpu;" ::: "memory");
        unsigned prev = atomicAdd(&g_bar_cnt, 1u);
        if (prev == (unsigned)(NBLK - 1)) {
            asm volatile("st.global.relaxed.gpu.u32 [%0], %1;"
                         :: "l"(&g_bar_cnt), "r"(0u) : "memory");
            asm volatile("fence.acq_rel.gpu;" ::: "memory");
            asm volatile("st.global.relaxed.gpu.u32 [%0], %1;"
                         :: "l"(&g_bar_gen), "r"(gen + 1u) : "memory");
        } else {
            unsigned cur;
            do {
                __nanosleep(64);
                asm volatile("ld.global.relaxed.gpu.u32 %0, [%1];"
                             : "=r"(cur) : "l"(&g_bar_gen));
            } while (cur == gen);
            asm volatile("fence.acq_rel.gpu;" ::: "memory");
        }
    }
    __syncthreads();
}

// rec smem layout (bytes)
#define SMEM_BIAS 0
#define SMEM_W    1024                   // W hi: [1024k][24n] bf16, 48B rows = 48 KB
#define SMEM_WLO  (1024 + 49152)         // 50176
#define SMEM_ACT  (50176 + 49152)        // 99328: 4 bufs x 32 KB block-shared chunks
#define ABUF      32768                  // [2 planes][128 rows][128 B (64 k)], SW128
#define SMEM_TOT  (99328 + 4 * ABUF)     // 230,400 B
// red buffer (48 KB) aliases SMEM_ACT after the k-loop.

// ============================================================================
// GRU recurrence on mma.sync. Block-shared k64 chunk staging (coalesced: each
// LDGSTS touches 4 lines), ring 4. Warp (p=w&3, q=w>>2): m [32p,32p+32) x n24,
// k-sub-slice q*16 of each 64-k chunk (k-split by q, merged via smem).
// ============================================================================
__global__ void __launch_bounds__(RTHR, 1)
gru_rec_mma(const float* __restrict__ w_hh, const float* __restrict__ b_ih,
            const float* __restrict__ b_hh)
{
    extern __shared__ char smem[];
    const int tid  = threadIdx.x;
    const int wid  = tid >> 5;
    const int lane = tid & 31;
    const int bid  = blockIdx.x;
    const int j0   = bid * 8;
    const int p    = wid & 3;
    const int q    = wid >> 2;
    const uint32_t sb = (uint32_t)__cvta_generic_to_shared(smem);

    // persistent W hi/lo: [k][n=gate*8+u], 48B rows (conflict-free for ldsm2t)
    for (int idx = tid; idx < 24 * HID; idx += RTHR) {
        int n = idx >> 10, k = idx & 1023;
        float w = w_hh[((size_t)(n >> 3) * HID + j0 + (n & 7)) * HID + k];
        __nv_bfloat16 hi = __float2bfloat16(w);
        __nv_bfloat16 lo = __float2bfloat16(w - __bfloat162float(hi));
        uint32_t a = (uint32_t)(k * 48 + n * 2);
        *(__nv_bfloat16*)(smem + SMEM_W   + a) = hi;
        *(__nv_bfloat16*)(smem + SMEM_WLO + a) = lo;
    }
    if (tid < 8) {
        float* sB = (float*)(smem + SMEM_BIAS);
        int j = j0 + tid;
        sB[tid]      = b_ih[j] + b_hh[j];
        sB[8 + tid]  = b_ih[HID + j] + b_hh[HID + j];
        sB[16 + tid] = b_ih[2 * HID + j];
        sB[24 + tid] = b_hh[2 * HID + j];
    }
    for (int idx = bid * RTHR + tid; idx < BATCH * HID; idx += NBLK * RTHR)
        g_hzero[idx] = __float2bfloat16(0.0f);
    __syncthreads();
    grid_bar();

    // lane-constant maps
    const int relrow = ((lane >> 3) & 1) * 8 + (lane & 7);
    const int segA   = lane >> 4;
    const uint32_t offA0 = SW128((uint32_t)((32 * p + relrow) * 128 + q * 32 + segA * 16));
    const uint32_t offA1 = SW128((uint32_t)((32 * p + 16 + relrow) * 128 + q * 32 + segA * 16));
    const int rbB = lane & 15;
    // coalesced staging map: 8 lanes cover one 128B row segment
    const int spl   = tid >> 8;          // plane: 0 = hi, 1 = lo
    const int sidx  = tid & 255;
    const int srow0 = sidx >> 3;         // rows srow0 + i*32, i = 0..3
    const int scol  = (sidx & 7) * 16;   // byte col within 128B
    const int selm  = (sidx & 7) * 8;    // bf16 elems
    const int eu = tid & 7;
    const int em = tid >> 3;

    for (int t = 0; t < T_STEPS; ++t) {
        const __nv_bfloat16* hi_src = t ? g_h1hi + (size_t)(t - 1) * BATCH * HID : g_hzero;
        const __nv_bfloat16* lo_src = t ? g_h1lo + (size_t)(t - 1) * BATCH * HID : g_hzero;
        const __nv_bfloat16* splane = spl ? lo_src : hi_src;

        // prologue: stage chunks 0..2 into bufs 0..2
        #pragma unroll
        for (int pre = 0; pre < 3; ++pre) {
            uint32_t bb = sb + SMEM_ACT + (uint32_t)(pre * ABUF + spl * 16384);
            #pragma unroll
            for (int i = 0; i < 4; ++i) {
                int row = srow0 + i * 32;
                cp16(bb + SW128((uint32_t)(row * 128 + scol)),
                     splane + (size_t)row * HID + pre * 64 + selm);
            }
            asm volatile("cp.async.commit_group;");
        }

        // epilogue operand prefetch
        float gir[2], giz[2], gin[2], hpv[2];
        #pragma unroll
        for (int it = 0; it < 2; ++it) {
            int m = em + it * 64;
            const float* gp = g_gi + ((size_t)t * BATCH + m) * GATES + j0 + eu;
            gir[it] = ldcg_f32(gp);
            giz[it] = ldcg_f32(gp + HID);
            gin[it] = ldcg_f32(gp + 2 * HID);
            hpv[it] = t ? ldcg_f32(g_h1 + ((size_t)(t - 1) * BATCH + m) * HID + j0 + eu)
                        : 0.0f;
        }

        float c[2][3][4];
        #pragma unroll
        for (int mt = 0; mt < 2; ++mt)
            #pragma unroll
            for (int g = 0; g < 3; ++g)
                #pragma unroll
                for (int r = 0; r < 4; ++r) c[mt][g][r] = 0.0f;

        #pragma unroll 1
        for (int i = 0; i < 16; ++i) {
            __syncthreads();   // all warps done consuming chunk i-1 (buf reused by i+3)
            if (i + 3 < 16) {
                uint32_t bb = sb + SMEM_ACT + (uint32_t)(((i + 3) & 3) * ABUF + spl * 16384);
                #pragma unroll
                for (int s = 0; s < 4; ++s) {
                    int row = srow0 + s * 32;
                    cp16(bb + SW128((uint32_t)(row * 128 + scol)),
                         splane + (size_t)row * HID + (i + 3) * 64 + selm);
                }
                asm volatile("cp.async.commit_group;");
                asm volatile("cp.async.wait_group 3;");
            } else {
                asm volatile("cp.async.wait_group 0;");
            }
            __syncthreads();   // chunk i visible to all warps

            // B fragments: k = i*64 + q*16 + rbB
            const int kb = i * 64 + q * 16;
            uint32_t bh[3][2], bl[3][2];
            #pragma unroll
            for (int g = 0; g < 3; ++g) {
                uint32_t a = (uint32_t)((kb + rbB) * 48 + g * 16);
                ldsm2t(bh[g], sb + SMEM_W + a);
                ldsm2t(bl[g], sb + SMEM_WLO + a);
            }
            const uint32_t abase = sb + SMEM_ACT + (uint32_t)((i & 3) * ABUF);
            #pragma unroll
            for (int mt = 0; mt < 2; ++mt) {
                uint32_t off = mt ? offA1 : offA0;
                uint32_t ah[4], al[4];
                ldsm4(ah, abase + off);
                ldsm4(al, abase + 16384 + off);
                #pragma unroll
                for (int g = 0; g < 3; ++g) {
                    mma16816(c[mt][g], ah, bh[g]);
                    mma16816(c[mt][g], al, bh[g]);
                    mma16816(c[mt][g], ah, bl[g]);
                }
            }
        }

        __syncthreads();   // act bufs idle; red aliases them
        float* red = (float*)(smem + SMEM_ACT);   // [128 m][24 n][4 q]
        {
            const int rr0 = p * 32 + (lane >> 2);
            const int c2  = (lane & 3) * 2;
            #pragma unroll
            for (int mt = 0; mt < 2; ++mt) {
                int rr = rr0 + mt * 16;
                #pragma unroll
                for (int g = 0; g < 3; ++g) {
                    int nn = g * 8 + c2;
                    red[(rr * 24 + nn) * 4 + q]           = c[mt][g][0];
                    red[(rr * 24 + nn + 1) * 4 + q]       = c[mt][g][1];
                    red[((rr + 8) * 24 + nn) * 4 + q]     = c[mt][g][2];
                    red[((rr + 8) * 24 + nn + 1) * 4 + q] = c[mt][g][3];
                }
            }
        }
        __syncthreads();

        {
            const float* sB = (const float*)(smem + SMEM_BIAS);
            #pragma unroll
            for (int it = 0; it < 2; ++it) {
                int m = em + it * 64;
                float4 vr = *(const float4*)(red + ((size_t)m * 24 + eu) * 4);
                float4 vz = *(const float4*)(red + ((size_t)m * 24 + 8 + eu) * 4);
                float4 vn = *(const float4*)(red + ((size_t)m * 24 + 16 + eu) * 4);
                float ghr = (vr.x + vr.y) + (vr.z + vr.w);
                float ghz = (vz.x + vz.y) + (vz.z + vz.w);
                float ghn = (vn.x + vn.y) + (vn.z + vn.w);
                float rg = 1.0f / (1.0f + expf(-(gir[it] + ghr + sB[eu])));
                float zg = 1.0f / (1.0f + expf(-(giz[it] + ghz + sB[8 + eu])));
                float ng = tanhf(gin[it] + sB[16 + eu] + rg * (ghn + sB[24 + eu]));
                float h  = (1.0f - zg) * ng + zg * hpv[it];

                __nv_bfloat16 hi = __float2bfloat16(h);
                __nv_bfloat16 lo = __float2bfloat16(h - __bfloat162float(hi));
                size_t o = ((size_t)t * BATCH + m) * HID + j0 + eu;
                g_h1hi[o] = hi;
                g_h1lo[o] = lo;
                g_h1[o]   = h;
            }
        }

        grid_bar();
    }
}

// ============================================================================
// Transpose + bf16-split w_ih1: [3072 n][1024 k] fp32 -> [k][n] hi/lo planes.
// ============================================================================
__global__ void __launch_bounds__(256)
conv_w(const float* __restrict__ w)
{
    __shared__ float tile[32][33];
    const int tx = threadIdx.x & 31;
    const int ty = threadIdx.x >> 5;       // 0..7
    const int k0 = blockIdx.x * 32;
    const int n0 = blockIdx.y * 32;
    #pragma unroll
    for (int r = 0; r < 4; ++r)
        tile[ty + r * 8][tx] = w[(size_t)(n0 + ty + r * 8) * HID + k0 + tx];
    __syncthreads();
    #pragma unroll
    for (int r = 0; r < 4; ++r) {
        float v = tile[tx][ty + r * 8];
        __nv_bfloat16 hi = __float2bfloat16(v);
        __nv_bfloat16 lo = __float2bfloat16(v - __bfloat162float(hi));
        size_t o = (size_t)(k0 + ty + r * 8) * GATES + n0 + tx;
        g_wbhi[o] = hi;
        g_wblo[o] = lo;
    }
}

// ============================================================================
// gi1 = h1 @ w_ih1^T on mma.sync (bf16 3-split). Tile 128m x 128n, K=1024.
// ============================================================================
#define GST 16384
__global__ void __launch_bounds__(512)
gemm_bf16_3s(float* __restrict__ C)
{
    extern __shared__ char gsm[];   // 4 * 16384
    const int tid  = threadIdx.x;
    const int wid  = tid >> 5;
    const int lane = tid & 31;
    const int m0 = blockIdx.y * 128;
    const int n0 = blockIdx.x * 128;
    const int p  = wid & 3;
    const int nq = wid >> 2;
    const uint32_t sb = (uint32_t)__cvta_generic_to_shared(gsm);

    const int relrow = ((lane >> 3) & 1) * 8 + (lane & 7);
    const int segA   = lane >> 4;
    const uint32_t offA0 = SWA((uint32_t)((p * 32 + relrow) * 32 + segA * 16));
    const uint32_t offA1 = SWA((uint32_t)((p * 32 + 16 + relrow) * 32 + segA * 16));
    const int rbB = lane & 15;
    uint32_t offB[4];
    #pragma unroll
    for (int nt = 0; nt < 4; ++nt)
        offB[nt] = (uint32_t)(8192 + rbB * 256) + SWR(rbB, (uint32_t)(nq * 64 + nt * 16));

    // staging maps
    const bool stA = (tid < 256);
    const int  apl = (tid >> 7) & 1;
    const int  am  = tid & 127;
    const int  bix = tid & 255;
    const int  bpl = bix >> 7;
    const int  brw = (bix & 127) >> 3;
    const int  bcs = (bix & 7) * 32;

    const __nv_bfloat16* Asrc = (apl ? g_h1lo : g_h1hi) + (size_t)(m0 + am) * HID;
    const __nv_bfloat16* Bpl  = (bpl ? g_wblo : g_wbhi) + n0 + bcs / 2;
    const uint32_t adst0 = (uint32_t)(apl * 4096) + SWA((uint32_t)(am * 32));
    const uint32_t adst1 = (uint32_t)(apl * 4096) + SWA((uint32_t)(am * 32 + 16));
    const uint32_t bdst0 = (uint32_t)(8192 + bpl * 4096 + brw * 256)
                         + SWR(brw, (uint32_t)bcs);
    const uint32_t bdst1 = (uint32_t)(8192 + bpl * 4096 + brw * 256)
                         + SWR(brw, (uint32_t)(bcs + 16));

    float c[2][4][4];
    #pragma unroll
    for (int mt = 0; mt < 2; ++mt)
        #pragma unroll
        for (int nt = 0; nt < 4; ++nt)
            #pragma unroll
            for (int r = 0; r < 4; ++r) c[mt][nt][r] = 0.0f;

    #pragma unroll
    for (int pre = 0; pre < 3; ++pre) {
        uint32_t base = sb + (uint32_t)(pre * GST);
        if (stA) {
            cp16(base + adst0, Asrc + pre * 16);
            cp16(base + adst1, Asrc + pre * 16 + 8);
        } else {
            const __nv_bfloat16* s = Bpl + (size_t)(pre * 16 + brw) * GATES;
            cp16(base + bdst0, s);
            cp16(base + bdst1, s + 8);
        }
        asm volatile("cp.async.commit_group;");
    }

    #pragma unroll 1
    for (int i = 0; i < 64; ++i) {
        __syncthreads();
        if (i + 3 < 64) {
            uint32_t base = sb + (uint32_t)(((i + 3) & 3) * GST);
            if (stA) {
                cp16(base + adst0, Asrc + (i + 3) * 16);
                cp16(base + adst1, Asrc + (i + 3) * 16 + 8);
            } else {
                const __nv_bfloat16* s = Bpl + (size_t)((i + 3) * 16 + brw) * GATES;
                cp16(base + bdst0, s);
                cp16(base + bdst1, s + 8);
            }
            asm volatile("cp.async.commit_group;");
            asm volatile("cp.async.wait_group 3;");
        } else {
            asm volatile("cp.async.wait_group 0;");
        }
        __syncthreads();

        const uint32_t base = sb + (uint32_t)((i & 3) * GST);
        uint32_t bh[4][2], bl[4][2];
        #pragma unroll
        for (int nt = 0; nt < 4; ++nt) {
            ldsm2t(bh[nt], base + offB[nt]);
            ldsm2t(bl[nt], base + offB[nt] + 4096);
        }
        #pragma unroll
        for (int mt = 0; mt < 2; ++mt) {
            uint32_t off = mt ? offA1 : offA0;
            uint32_t ah[4], al[4];
            ldsm4(ah, base + off);
            ldsm4(al, base + 4096 + off);
            #pragma unroll
            for (int nt = 0; nt < 4; ++nt) {
                mma16816(c[mt][nt], ah, bh[nt]);
                mma16816(c[mt][nt], al, bh[nt]);
                mma16816(c[mt][nt], ah, bl[nt]);
            }
        }
    }

    #pragma unroll
    for (int mt = 0; mt < 2; ++mt) {
        int row = m0 + p * 32 + mt * 16 + (lane >> 2);
        #pragma unroll
        for (int nt = 0; nt < 4; ++nt) {
            int col = n0 + nq * 32 + nt * 8 + (lane & 3) * 2;
            *(float2*)(C + (size_t)row * GATES + col) =
                make_float2(c[mt][nt][0], c[mt][nt][1]);
            *(float2*)(C + (size_t)(row + 8) * GATES + col) =
                make_float2(c[mt][nt][2], c[mt][nt][3]);
        }
    }
}

// ============================================================================
// gi0 = x @ w_ih0^T  (K=64, fp32 f32x2)
// ============================================================================
#define GKC 16
__global__ void __launch_bounds__(256)
gemm_tn_f32x2(const float* __restrict__ A, const float* __restrict__ B,
              float* __restrict__ C, int M, int N, int K)
{
    __shared__ float sA[GKC][132];
    __shared__ float sB[GKC][132];
    const int tid = threadIdx.x;
    const int m0  = blockIdx.y * 128;
    const int n0  = blockIdx.x * 128;
    const int ty  = tid >> 4, tx = tid & 15;
    const int sr = tid >> 1;
    const int sk = (tid & 1) * 8;

    u64 acc[4][8];
    #pragma unroll
    for (int p = 0; p < 4; ++p)
        #pragma unroll
        for (int c = 0; c < 8; ++c) acc[p][c] = 0ull;

    const float* Ag = A + (size_t)(m0 + sr) * K + sk;
    const float* Bg = B + (size_t)(n0 + sr) * K + sk;
    float4 a0 = ldcg_f32x4(Ag);
    float4 a1 = ldcg_f32x4(Ag + 4);
    float4 b0 = ldcg_f32x4(Bg);
    float4 b1 = ldcg_f32x4(Bg + 4);

    for (int kc = 0; kc < K; kc += GKC) {
        sA[sk + 0][sr] = a0.x; sA[sk + 1][sr] = a0.y;
        sA[sk + 2][sr] = a0.z; sA[sk + 3][sr] = a0.w;
        sA[sk + 4][sr] = a1.x; sA[sk + 5][sr] = a1.y;
        sA[sk + 6][sr] = a1.z; sA[sk + 7][sr] = a1.w;
        sB[sk + 0][sr] = b0.x; sB[sk + 1][sr] = b0.y;
        sB[sk + 2][sr] = b0.z; sB[sk + 3][sr] = b0.w;
        sB[sk + 4][sr] = b1.x; sB[sk + 5][sr] = b1.y;
        sB[sk + 6][sr] = b1.z; sB[sk + 7][sr] = b1.w;
        if (kc + GKC < K) {
            Ag += GKC; Bg += GKC;
            a0 = ldcg_f32x4(Ag);
            a1 = ldcg_f32x4(Ag + 4);
            b0 = ldcg_f32x4(Bg);
            b1 = ldcg_f32x4(Bg + 4);
        }
        __syncthreads();
        #pragma unroll
        for (int kk = 0; kk < GKC; ++kk) {
            ulonglong2 aa = *(const ulonglong2*)(&sA[kk][ty * 8]);
            ulonglong2 ab = *(const ulonglong2*)(&sA[kk][ty * 8 + 4]);
            float4 bv0 = *(const float4*)(&sB[kk][tx * 8]);
            float4 bv1 = *(const float4*)(&sB[kk][tx * 8 + 4]);
            float bs[8] = {bv0.x, bv0.y, bv0.z, bv0.w, bv1.x, bv1.y, bv1.z, bv1.w};
            #pragma unroll
            for (int c = 0; c < 8; ++c) {
                u64 bd = dup2(bs[c]);
                fma2(acc[0][c], aa.x, bd);
                fma2(acc[1][c], aa.y, bd);
                fma2(acc[2][c], ab.x, bd);
                fma2(acc[3][c], ab.y, bd);
            }
        }
        __syncthreads();
    }

    #pragma unroll
    for (int p = 0; p < 4; ++p) {
        float2 v[8];
        #pragma unroll
        for (int c = 0; c < 8; ++c) v[c] = unpk(acc[p][c]);
        int row0 = m0 + ty * 8 + p * 2;
        float* c0 = C + (size_t)row0 * N + n0 + tx * 8;
        float* c1 = c0 + N;
        *(float4*)(c0)     = make_float4(v[0].x, v[1].x, v[2].x, v[3].x);
        *(float4*)(c0 + 4) = make_float4(v[4].x, v[5].x, v[6].x, v[7].x);
        *(float4*)(c1)     = make_float4(v[0].y, v[1].y, v[2].y, v[3].y);
        *(float4*)(c1 + 4) = make_float4(v[4].y, v[5].y, v[6].y, v[7].y);
    }
}

// ============================================================================
// out[t,b,o] = h2[t,b,:] . w_lin[o,:] + b_lin[o]  (h2 in g_h1)
// ============================================================================
__global__ void __launch_bounds__(256)
out_linear(const float* __restrict__ w_lin, const float* __restrict__ b_lin,
           float* __restrict__ out)
{
    __shared__ float sA[16][68];
    __shared__ float sB[16][68];
    const int tid = threadIdx.x;
    const size_t rb = (size_t)blockIdx.x * 64;
    const int ty = tid >> 4;
    const int tx = tid & 15;
    const int li   = tid * 4;
    const int srow = li >> 4;
    const int skk  = li & 15;

    float acc[4][4] = {};

    for (int kc = 0; kc < HID; kc += 16) {
        __syncthreads();
        float4 va = ldcg_f32x4(g_h1 + (rb + srow) * HID + kc + skk);
        sA[skk + 0][srow] = va.x; sA[skk + 1][srow] = va.y;
        sA[skk + 2][srow] = va.z; sA[skk + 3][srow] = va.w;
        float4 vb = *(const float4*)(w_lin + (size_t)srow * HID + kc + skk);
        sB[skk + 0][srow] = vb.x; sB[skk + 1][srow] = vb.y;
        sB[skk + 2][srow] = vb.z; sB[skk + 3][srow] = vb.w;
        __syncthreads();
        #pragma unroll
        for (int kk = 0; kk < 16; ++kk) {
            float4 a = *(const float4*)&sA[kk][ty * 4];
            float4 b = *(const float4*)&sB[kk][tx * 4];
            acc[0][0] = fmaf(a.x, b.x, acc[0][0]); acc[0][1] = fmaf(a.x, b.y, acc[0][1]);
            acc[0][2] = fmaf(a.x, b.z, acc[0][2]); acc[0][3] = fmaf(a.x, b.w, acc[0][3]);
            acc[1][0] = fmaf(a.y, b.x, acc[1][0]); acc[1][1] = fmaf(a.y, b.y, acc[1][1]);
            acc[1][2] = fmaf(a.y, b.z, acc[1][2]); acc[1][3] = fmaf(a.y, b.w, acc[1][3]);
            acc[2][0] = fmaf(a.z, b.x, acc[2][0]); acc[2][1] = fmaf(a.z, b.y, acc[2][1]);
            acc[2][2] = fmaf(a.z, b.z, acc[2][2]); acc[2][3] = fmaf(a.z, b.w, acc[2][3]);
            acc[3][0] = fmaf(a.w, b.x, acc[3][0]); acc[3][1] = fmaf(a.w, b.y, acc[3][1]);
            acc[3][2] = fmaf(a.w, b.z, acc[3][2]); acc[3][3] = fmaf(a.w, b.w, acc[3][3]);
        }
    }

    #pragma unroll
    for (int i = 0; i < 4; ++i) {
        float4 o4;
        o4.x = acc[i][0] + b_lin[tx * 4 + 0];
        o4.y = acc[i][1] + b_lin[tx * 4 + 1];
        o4.z = acc[i][2] + b_lin[tx * 4 + 2];
        o4.w = acc[i][3] + b_lin[tx * 4 + 3];
        *(float4*)(out + (rb + ty * 4 + i) * OUT_DIM + tx * 4) = o4;
    }
}

extern "C" void kernel_launch(void* const* d_in, const int* in_sizes, int n_in,
                              void* d_out, int out_size)
{
    const float* x     = (const float*)d_in[0];
    const float* w_ih0 = (const float*)d_in[1];
    const float* w_hh0 = (const float*)d_in[2];
    const float* b_ih0 = (const float*)d_in[3];
    const float* b_hh0 = (const float*)d_in[4];
    const float* w_ih1 = (const float*)d_in[5];
    const float* w_hh1 = (const float*)d_in[6];
    const float* b_ih1 = (const float*)d_in[7];
    const float* b_hh1 = (const float*)d_in[8];
    const float* w_lin = (const float*)d_in[9];
    const float* b_lin = (const float*)d_in[10];
    float* out = (float*)d_out;
    (void)in_sizes; (void)n_in; (void)out_size;

    float *gi_ptr;
    cudaGetSymbolAddress((void**)&gi_ptr, g_gi);

    cudaFuncSetAttribute(gru_rec_mma, cudaFuncAttributeMaxDynamicSharedMemorySize, SMEM_TOT);
    cudaFuncSetAttribute(gemm_bf16_3s, cudaFuncAttributeMaxDynamicSharedMemorySize, 4 * GST);

    // w_ih1 transpose + split (independent of layer 0)
    conv_w<<<dim3(HID / 32, GATES / 32), 256>>>(w_ih1);

    // layer 0
    gemm_tn_f32x2<<<dim3(GATES / 128, MROWS / 128), 256>>>(x, w_ih0, gi_ptr,
                                                           MROWS, GATES, IN_DIM);
    gru_rec_mma<<<NBLK, RTHR, SMEM_TOT>>>(w_hh0, b_ih0, b_hh0);

    // layer 1
    gemm_bf16_3s<<<dim3(GATES / 128, MROWS / 128), 512, 4 * GST>>>(gi_ptr);
    gru_rec_mma<<<NBLK, RTHR, SMEM_TOT>>>(w_hh1, b_ih1, b_hh1);

    // time-distributed linear
    out_linear<<<MROWS / 64, 256>>>(w_lin, b_lin, out);
}